// round 1
// baseline (speedup 1.0000x reference)
#include <cuda_runtime.h>
#include <math_constants.h>

#define HIDDEN 768
#define NH     12
#define DH     64
#define BATCH  4
#define SEQ    2048
#define MTOT   (BATCH*SEQ)   // 8192

// Scratch (allocation-free rule: __device__ globals)
__device__ float g_q[(size_t)MTOT * HIDDEN];
__device__ float g_k[(size_t)MTOT * HIDDEN];
__device__ float g_v[(size_t)MTOT * HIDDEN];
__device__ float g_ctx[(size_t)MTOT * HIDDEN];

// ---------------------------------------------------------------------------
// Tiled GEMM body: O[m,n] = sum_k X[m,k] * W[n,k]   (x @ W^T, torch Linear)
// 64x64 output tile per block, BK=16, 256 threads, 4x4 per thread.
// ---------------------------------------------------------------------------
__device__ __forceinline__ void gemm_tile(const float* __restrict__ X,
                                          const float* __restrict__ W,
                                          float* __restrict__ O)
{
    __shared__ float Xs[16][68];   // [k][m] transposed, padded
    __shared__ float Ws[16][68];   // [k][n] transposed, padded

    const int tid = threadIdx.x;
    const int tx  = tid & 15;
    const int ty  = tid >> 4;
    const int bm  = blockIdx.y << 6;
    const int bn  = blockIdx.x << 6;
    const int lr  = tid >> 2;          // 0..63 tile row
    const int lc  = (tid & 3) << 2;    // 0,4,8,12 k-col (float4)

    float acc[4][4];
#pragma unroll
    for (int i = 0; i < 4; i++)
#pragma unroll
        for (int j = 0; j < 4; j++) acc[i][j] = 0.0f;

    const float* xp = X + (size_t)(bm + lr) * HIDDEN + lc;
    const float* wp = W + (size_t)(bn + lr) * HIDDEN + lc;

    for (int k0 = 0; k0 < HIDDEN; k0 += 16) {
        // prefetch before sync
        float4 xv = *(const float4*)(xp + k0);
        float4 wv = *(const float4*)(wp + k0);
        __syncthreads();
        Xs[lc + 0][lr] = xv.x; Xs[lc + 1][lr] = xv.y;
        Xs[lc + 2][lr] = xv.z; Xs[lc + 3][lr] = xv.w;
        Ws[lc + 0][lr] = wv.x; Ws[lc + 1][lr] = wv.y;
        Ws[lc + 2][lr] = wv.z; Ws[lc + 3][lr] = wv.w;
        __syncthreads();
#pragma unroll
        for (int kk = 0; kk < 16; kk++) {
            float4 a = *(const float4*)&Xs[kk][ty << 2];
            float4 b = *(const float4*)&Ws[kk][tx << 2];
            float av[4] = {a.x, a.y, a.z, a.w};
            float bv[4] = {b.x, b.y, b.z, b.w};
#pragma unroll
            for (int i = 0; i < 4; i++)
#pragma unroll
                for (int j = 0; j < 4; j++)
                    acc[i][j] = fmaf(av[i], bv[j], acc[i][j]);
        }
    }

#pragma unroll
    for (int i = 0; i < 4; i++) {
        float4 r = make_float4(acc[i][0], acc[i][1], acc[i][2], acc[i][3]);
        *(float4*)(O + (size_t)(bm + (ty << 2) + i) * HIDDEN + bn + (tx << 2)) = r;
    }
}

__global__ __launch_bounds__(256) void qkv_kernel(const float* __restrict__ X,
                                                  const float* __restrict__ Wq,
                                                  const float* __restrict__ Wk,
                                                  const float* __restrict__ Wv)
{
    const float* W;
    float* O;
    if (blockIdx.z == 0)      { W = Wq; O = g_q; }
    else if (blockIdx.z == 1) { W = Wk; O = g_k; }
    else                      { W = Wv; O = g_v; }
    gemm_tile(X, W, O);
}

__global__ __launch_bounds__(256) void proj_kernel(const float* __restrict__ Wo,
                                                   float* __restrict__ out)
{
    gemm_tile(g_ctx, Wo, out);
}

// ---------------------------------------------------------------------------
// Flash attention: one (b, h, 64-query tile) per block. 256 threads (16x16).
// Online softmax; P staged through shared for the PV GEMM.
// Shared: Qs_t[64][68] + Ks_t[64][68] + Vs[64][68] + Ps_t[64][68] = 69632 B.
// ---------------------------------------------------------------------------
#define SROW 68
#define ATTN_SMEM (4 * 64 * SROW * (int)sizeof(float))

extern __shared__ float smem_attn[];

__global__ __launch_bounds__(256) void attn_kernel()
{
    float* Qs = smem_attn;           // Qs[d*SROW + r]   (transposed)
    float* Ks = Qs + 64 * SROW;      // Ks[d*SROW + c]   (transposed)
    float* Vs = Ks + 64 * SROW;      // Vs[c*SROW + d]   (direct)
    float* Ps = Vs + 64 * SROW;      // Ps[c*SROW + r]   (transposed)

    const int tid = threadIdx.x;
    const int tx  = tid & 15;
    const int ty  = tid >> 4;
    const int bh  = blockIdx.y;
    const int b   = bh / NH;
    const int h   = bh % NH;
    const int q0  = blockIdx.x << 6;

    const float* Qg = g_q + (size_t)b * SEQ * HIDDEN + h * DH;
    const float* Kg = g_k + (size_t)b * SEQ * HIDDEN + h * DH;
    const float* Vg = g_v + (size_t)b * SEQ * HIDDEN + h * DH;

    const int lr = tid >> 2;          // 0..63 token row in tile
    const int lc = (tid & 3) << 4;    // 0,16,32,48 head-dim base

    // Load Q tile (scaled by 1/sqrt(64)) transposed into shared.
#pragma unroll
    for (int u = 0; u < 4; u++) {
        int d = lc + (u << 2);
        float4 v = *(const float4*)&Qg[(size_t)(q0 + lr) * HIDDEN + d];
        Qs[(d + 0) * SROW + lr] = v.x * 0.125f;
        Qs[(d + 1) * SROW + lr] = v.y * 0.125f;
        Qs[(d + 2) * SROW + lr] = v.z * 0.125f;
        Qs[(d + 3) * SROW + lr] = v.w * 0.125f;
    }

    float o[4][4];
#pragma unroll
    for (int i = 0; i < 4; i++)
#pragma unroll
        for (int j = 0; j < 4; j++) o[i][j] = 0.0f;
    float m_i[4] = {-CUDART_INF_F, -CUDART_INF_F, -CUDART_INF_F, -CUDART_INF_F};
    float l_i[4] = {0.0f, 0.0f, 0.0f, 0.0f};

    for (int kt = 0; kt < SEQ; kt += 64) {
        // Prefetch K/V tiles into registers before the sync.
        float4 kreg[4], vreg[4];
#pragma unroll
        for (int u = 0; u < 4; u++) {
            int d = lc + (u << 2);
            kreg[u] = *(const float4*)&Kg[(size_t)(kt + lr) * HIDDEN + d];
            vreg[u] = *(const float4*)&Vg[(size_t)(kt + lr) * HIDDEN + d];
        }
        __syncthreads();   // previous iteration done reading Ks/Vs/Ps
#pragma unroll
        for (int u = 0; u < 4; u++) {
            int d = lc + (u << 2);
            Ks[(d + 0) * SROW + lr] = kreg[u].x;
            Ks[(d + 1) * SROW + lr] = kreg[u].y;
            Ks[(d + 2) * SROW + lr] = kreg[u].z;
            Ks[(d + 3) * SROW + lr] = kreg[u].w;
            *(float4*)&Vs[lr * SROW + d] = vreg[u];
        }
        __syncthreads();

        // S = (Q * 1/8) . K^T   : 4x4 tile per thread
        float s[4][4];
#pragma unroll
        for (int i = 0; i < 4; i++)
#pragma unroll
            for (int j = 0; j < 4; j++) s[i][j] = 0.0f;
#pragma unroll 16
        for (int kk = 0; kk < 64; kk++) {
            float4 a = *(const float4*)&Qs[kk * SROW + (ty << 2)];
            float4 bb = *(const float4*)&Ks[kk * SROW + (tx << 2)];
            float av[4] = {a.x, a.y, a.z, a.w};
            float bv[4] = {bb.x, bb.y, bb.z, bb.w};
#pragma unroll
            for (int i = 0; i < 4; i++)
#pragma unroll
                for (int j = 0; j < 4; j++)
                    s[i][j] = fmaf(av[i], bv[j], s[i][j]);
        }

        // Online softmax per row (rows shared by the 16 threads of one ty).
#pragma unroll
        for (int i = 0; i < 4; i++) {
            float tm = fmaxf(fmaxf(s[i][0], s[i][1]), fmaxf(s[i][2], s[i][3]));
            tm = fmaxf(tm, __shfl_xor_sync(0xffffffffu, tm, 8, 16));
            tm = fmaxf(tm, __shfl_xor_sync(0xffffffffu, tm, 4, 16));
            tm = fmaxf(tm, __shfl_xor_sync(0xffffffffu, tm, 2, 16));
            tm = fmaxf(tm, __shfl_xor_sync(0xffffffffu, tm, 1, 16));
            float mnew  = fmaxf(m_i[i], tm);
            float alpha = __expf(m_i[i] - mnew);   // -inf -> 0 on first tile
            float ps = 0.0f;
#pragma unroll
            for (int j = 0; j < 4; j++) {
                s[i][j] = __expf(s[i][j] - mnew);
                ps += s[i][j];
            }
            ps += __shfl_xor_sync(0xffffffffu, ps, 8, 16);
            ps += __shfl_xor_sync(0xffffffffu, ps, 4, 16);
            ps += __shfl_xor_sync(0xffffffffu, ps, 2, 16);
            ps += __shfl_xor_sync(0xffffffffu, ps, 1, 16);
            l_i[i] = l_i[i] * alpha + ps;
            m_i[i] = mnew;
#pragma unroll
            for (int j = 0; j < 4; j++) o[i][j] *= alpha;
        }

        // Stage P to shared (transposed: Ps[c][r]).
#pragma unroll
        for (int j = 0; j < 4; j++)
#pragma unroll
            for (int i = 0; i < 4; i++)
                Ps[((tx << 2) + j) * SROW + (ty << 2) + i] = s[i][j];
        __syncthreads();

        // O += P . V
#pragma unroll 16
        for (int c = 0; c < 64; c++) {
            float4 a = *(const float4*)&Ps[c * SROW + (ty << 2)];
            float4 bb = *(const float4*)&Vs[c * SROW + (tx << 2)];
            float av[4] = {a.x, a.y, a.z, a.w};
            float bv[4] = {bb.x, bb.y, bb.z, bb.w};
#pragma unroll
            for (int i = 0; i < 4; i++)
#pragma unroll
                for (int j = 0; j < 4; j++)
                    o[i][j] = fmaf(av[i], bv[j], o[i][j]);
        }
    }

    // Normalize and write context (layout [b, t, h*64 + d]).
    float* Og = g_ctx + (size_t)b * SEQ * HIDDEN + h * DH;
#pragma unroll
    for (int i = 0; i < 4; i++) {
        float inv = 1.0f / l_i[i];
        float4 r = make_float4(o[i][0] * inv, o[i][1] * inv, o[i][2] * inv, o[i][3] * inv);
        *(float4*)&Og[(size_t)(q0 + (ty << 2) + i) * HIDDEN + (tx << 2)] = r;
    }
}

// ---------------------------------------------------------------------------
extern "C" void kernel_launch(void* const* d_in, const int* in_sizes, int n_in,
                              void* d_out, int out_size)
{
    const float* x  = (const float*)d_in[0];
    const float* wq = (const float*)d_in[1];
    const float* wk = (const float*)d_in[2];
    const float* wv = (const float*)d_in[3];
    const float* wo = (const float*)d_in[4];
    float* out = (float*)d_out;

    // Allow >48KB dynamic shared for the attention kernel (idempotent).
    cudaFuncSetAttribute(attn_kernel, cudaFuncAttributeMaxDynamicSharedMemorySize,
                         ATTN_SMEM);

    dim3 gqkv(HIDDEN / 64, MTOT / 64, 3);      // (12, 128, 3)
    qkv_kernel<<<gqkv, 256>>>(x, wq, wk, wv);

    dim3 gattn(SEQ / 64, BATCH * NH);          // (32, 48)
    attn_kernel<<<gattn, 256, ATTN_SMEM>>>();

    dim3 gproj(HIDDEN / 64, MTOT / 64);        // (12, 128)
    proj_kernel<<<gproj, 256>>>(wo, out);
}

// round 3
// speedup vs baseline: 1.3778x; 1.3778x over previous
#include <cuda_runtime.h>
#include <cuda_bf16.h>
#include <math_constants.h>
#include <cstdint>

#define HIDDEN 768
#define NH     12
#define DH     64
#define BATCH  4
#define SEQ    2048
#define MTOT   (BATCH*SEQ)   // 8192

// ---------------------------------------------------------------------------
// Scratch (__device__ globals: allocation-free rule)
// ---------------------------------------------------------------------------
__device__ float g_q[(size_t)MTOT * HIDDEN];
__device__ float g_k[(size_t)MTOT * HIDDEN];
__device__ float g_v[(size_t)MTOT * HIDDEN];
__device__ float g_ctx[(size_t)MTOT * HIDDEN];

__device__ __nv_bfloat16 g_xhi[(size_t)MTOT * HIDDEN];
__device__ __nv_bfloat16 g_xlo[(size_t)MTOT * HIDDEN];
__device__ __nv_bfloat16 g_chi[(size_t)MTOT * HIDDEN];
__device__ __nv_bfloat16 g_clo[(size_t)MTOT * HIDDEN];
__device__ __nv_bfloat16 g_whi[4][(size_t)HIDDEN * HIDDEN];
__device__ __nv_bfloat16 g_wlo[4][(size_t)HIDDEN * HIDDEN];

// ---------------------------------------------------------------------------
// Warp-MMA primitives (baseline PTX: works on compute_103 target)
// ---------------------------------------------------------------------------
__device__ __forceinline__ uint32_t smem_u32(const void* p) {
    uint32_t a;
    asm("{ .reg .u64 t; cvta.to.shared.u64 t, %1; cvt.u32.u64 %0, t; }"
        : "=r"(a) : "l"(p));
    return a;
}

__device__ __forceinline__ void mma_bf16(float* d, const uint32_t* a, const uint32_t* b) {
    asm volatile(
        "mma.sync.aligned.m16n8k16.row.col.f32.bf16.bf16.f32 "
        "{%0,%1,%2,%3}, {%4,%5,%6,%7}, {%8,%9}, {%0,%1,%2,%3};"
        : "+f"(d[0]), "+f"(d[1]), "+f"(d[2]), "+f"(d[3])
        : "r"(a[0]), "r"(a[1]), "r"(a[2]), "r"(a[3]), "r"(b[0]), "r"(b[1]));
}

__device__ __forceinline__ void ldsm_x4(uint32_t* r, uint32_t addr) {
    asm volatile("ldmatrix.sync.aligned.m8n8.x4.shared.b16 {%0,%1,%2,%3}, [%4];"
                 : "=r"(r[0]), "=r"(r[1]), "=r"(r[2]), "=r"(r[3]) : "r"(addr));
}

__device__ __forceinline__ void ldsm_x2(uint32_t* r, uint32_t addr) {
    asm volatile("ldmatrix.sync.aligned.m8n8.x2.shared.b16 {%0,%1}, [%2];"
                 : "=r"(r[0]), "=r"(r[1]) : "r"(addr));
}

// ---------------------------------------------------------------------------
// fp32 -> bf16 hi/lo split (2-term): x = hi + lo + O(2^-17 x)
// ---------------------------------------------------------------------------
__global__ __launch_bounds__(256) void split_kernel(const float* __restrict__ src,
                                                    __nv_bfloat16* __restrict__ hi,
                                                    __nv_bfloat16* __restrict__ lo,
                                                    int n4)
{
    int i = blockIdx.x * blockDim.x + threadIdx.x;
    if (i >= n4) return;
    float4 v = ((const float4*)src)[i];
    __nv_bfloat16 h0 = __float2bfloat16(v.x);
    __nv_bfloat16 h1 = __float2bfloat16(v.y);
    __nv_bfloat16 h2 = __float2bfloat16(v.z);
    __nv_bfloat16 h3 = __float2bfloat16(v.w);
    __nv_bfloat16 l0 = __float2bfloat16(v.x - __bfloat162float(h0));
    __nv_bfloat16 l1 = __float2bfloat16(v.y - __bfloat162float(h1));
    __nv_bfloat16 l2 = __float2bfloat16(v.z - __bfloat162float(h2));
    __nv_bfloat16 l3 = __float2bfloat16(v.w - __bfloat162float(h3));
    __nv_bfloat162 ph0; ph0.x = h0; ph0.y = h1;
    __nv_bfloat162 ph1; ph1.x = h2; ph1.y = h3;
    __nv_bfloat162 pl0; pl0.x = l0; pl0.y = l1;
    __nv_bfloat162 pl1; pl1.x = l2; pl1.y = l3;
    ((__nv_bfloat162*)hi)[2 * i + 0] = ph0;
    ((__nv_bfloat162*)hi)[2 * i + 1] = ph1;
    ((__nv_bfloat162*)lo)[2 * i + 0] = pl0;
    ((__nv_bfloat162*)lo)[2 * i + 1] = pl1;
}

// ---------------------------------------------------------------------------
// HMMA bf16-split GEMM: C[M,N] = A[M,K] @ B[N,K]^T  (fp32 out, K=768)
// 128x128 CTA tile, BK=32, 8 warps (2x4), warp tile 64x32.
// Swizzle: 16B chunk index  c ^ ((row>>1)&3)  -> conflict-free st.128 + ldmatrix.
// ---------------------------------------------------------------------------
#define KCH (HIDDEN / 32)    // 24 K-chunks

__device__ __forceinline__ void hmma_gemm(const __nv_bfloat16* __restrict__ Ahi,
                                          const __nv_bfloat16* __restrict__ Alo,
                                          const __nv_bfloat16* __restrict__ Bhi,
                                          const __nv_bfloat16* __restrict__ Blo,
                                          float* __restrict__ C)
{
    __shared__ uint4 sAh[512], sAl[512], sBh[512], sBl[512];   // 128 rows x 4 chunks

    const int tid  = threadIdx.x;
    const int lane = tid & 31;
    const int wid  = tid >> 5;
    const int wm   = (wid & 1) * 64;
    const int wn   = (wid >> 1) * 32;
    const int bm   = blockIdx.y * 128;
    const int bn   = blockIdx.x * 128;

    // staging: two 16B units per thread per array
    const int r0 = tid >> 2;            // 0..63
    const int c0 = tid & 3;
    const int dst0 = r0 * 4 + (c0 ^ ((r0 >> 1) & 3));
    const int dst1 = dst0 + 256;        // row+64 keeps same xor key

    const uint4* Ah4 = (const uint4*)Ahi;
    const uint4* Al4 = (const uint4*)Alo;
    const uint4* Bh4 = (const uint4*)Bhi;
    const uint4* Bl4 = (const uint4*)Blo;
    const int rowstride4 = HIDDEN / 8;  // 96 uint4 per row
    const size_t srcA0 = (size_t)(bm + r0) * rowstride4 + c0;
    const size_t srcA1 = (size_t)(bm + r0 + 64) * rowstride4 + c0;
    const size_t srcB0 = (size_t)(bn + r0) * rowstride4 + c0;
    const size_t srcB1 = (size_t)(bn + r0 + 64) * rowstride4 + c0;

    const uint32_t bAh = smem_u32(sAh);
    const uint32_t bAl = smem_u32(sAl);
    const uint32_t bBh = smem_u32(sBh);
    const uint32_t bBl = smem_u32(sBl);

    // ldmatrix offsets (per mi / ni / ks)
    uint32_t offA[2][4], offB[2][4];
#pragma unroll
    for (int mi = 0; mi < 4; mi++) {
        int rowA = wm + mi * 16 + (lane & 15);
        int keyA = (rowA >> 1) & 3;
#pragma unroll
        for (int ks = 0; ks < 2; ks++) {
            int c = ks * 2 + (lane >> 4);
            offA[ks][mi] = rowA * 64 + ((c ^ keyA) << 4);
        }
    }
#pragma unroll
    for (int ni = 0; ni < 4; ni++) {
        int rowB = wn + ni * 8 + (lane & 7);
        int keyB = (rowB >> 1) & 3;
#pragma unroll
        for (int ks = 0; ks < 2; ks++) {
            int c = ks * 2 + ((lane >> 3) & 1);
            offB[ks][ni] = rowB * 64 + ((c ^ keyB) << 4);
        }
    }

    float acc[4][4][4];
#pragma unroll
    for (int mi = 0; mi < 4; mi++)
#pragma unroll
        for (int ni = 0; ni < 4; ni++)
#pragma unroll
            for (int t = 0; t < 4; t++) acc[mi][ni][t] = 0.0f;

    for (int kc = 0; kc < KCH; kc++) {
        const size_t ko = (size_t)kc * 4;
        uint4 vah0 = Ah4[srcA0 + ko], vah1 = Ah4[srcA1 + ko];
        uint4 val0 = Al4[srcA0 + ko], val1 = Al4[srcA1 + ko];
        uint4 vbh0 = Bh4[srcB0 + ko], vbh1 = Bh4[srcB1 + ko];
        uint4 vbl0 = Bl4[srcB0 + ko], vbl1 = Bl4[srcB1 + ko];
        __syncthreads();   // previous chunk fully consumed via ldmatrix
        sAh[dst0] = vah0; sAh[dst1] = vah1;
        sAl[dst0] = val0; sAl[dst1] = val1;
        sBh[dst0] = vbh0; sBh[dst1] = vbh1;
        sBl[dst0] = vbl0; sBl[dst1] = vbl1;
        __syncthreads();

#pragma unroll
        for (int ks = 0; ks < 2; ks++) {
            uint32_t ah[4][4], al[4][4], bh[4][2], bl[4][2];
#pragma unroll
            for (int mi = 0; mi < 4; mi++) {
                ldsm_x4(ah[mi], bAh + offA[ks][mi]);
                ldsm_x4(al[mi], bAl + offA[ks][mi]);
            }
#pragma unroll
            for (int ni = 0; ni < 4; ni++) {
                ldsm_x2(bh[ni], bBh + offB[ks][ni]);
                ldsm_x2(bl[ni], bBl + offB[ks][ni]);
            }
#pragma unroll
            for (int mi = 0; mi < 4; mi++)
#pragma unroll
                for (int ni = 0; ni < 4; ni++) {
                    mma_bf16(acc[mi][ni], ah[mi], bh[ni]);
                    mma_bf16(acc[mi][ni], ah[mi], bl[ni]);
                    mma_bf16(acc[mi][ni], al[mi], bh[ni]);
                }
        }
    }

    // epilogue: fragment layout m16n8 -> (row = lane/4 (+8), col = (lane%4)*2)
#pragma unroll
    for (int mi = 0; mi < 4; mi++) {
        int row = bm + wm + mi * 16 + (lane >> 2);
#pragma unroll
        for (int ni = 0; ni < 4; ni++) {
            int col = bn + wn + ni * 8 + ((lane & 3) << 1);
            float2 v0 = make_float2(acc[mi][ni][0], acc[mi][ni][1]);
            float2 v1 = make_float2(acc[mi][ni][2], acc[mi][ni][3]);
            *(float2*)(C + (size_t)row * HIDDEN + col) = v0;
            *(float2*)(C + (size_t)(row + 8) * HIDDEN + col) = v1;
        }
    }
}

__global__ __launch_bounds__(256) void qkv_mma_kernel()
{
    const int z = blockIdx.z;
    float* O = (z == 0) ? g_q : (z == 1) ? g_k : g_v;
    hmma_gemm(g_xhi, g_xlo, g_whi[z], g_wlo[z], O);
}

__global__ __launch_bounds__(256) void proj_mma_kernel(float* __restrict__ out)
{
    hmma_gemm(g_chi, g_clo, g_whi[3], g_wlo[3], out);
}

// ---------------------------------------------------------------------------
// Flash attention (SIMT fp32, unchanged)
// ---------------------------------------------------------------------------
#define SROW 68
#define ATTN_SMEM (4 * 64 * SROW * (int)sizeof(float))

extern __shared__ float smem_attn[];

__global__ __launch_bounds__(256) void attn_kernel()
{
    float* Qs = smem_attn;
    float* Ks = Qs + 64 * SROW;
    float* Vs = Ks + 64 * SROW;
    float* Ps = Vs + 64 * SROW;

    const int tid = threadIdx.x;
    const int tx  = tid & 15;
    const int ty  = tid >> 4;
    const int bh  = blockIdx.y;
    const int b   = bh / NH;
    const int h   = bh % NH;
    const int q0  = blockIdx.x << 6;

    const float* Qg = g_q + (size_t)b * SEQ * HIDDEN + h * DH;
    const float* Kg = g_k + (size_t)b * SEQ * HIDDEN + h * DH;
    const float* Vg = g_v + (size_t)b * SEQ * HIDDEN + h * DH;

    const int lr = tid >> 2;
    const int lc = (tid & 3) << 4;

#pragma unroll
    for (int u = 0; u < 4; u++) {
        int d = lc + (u << 2);
        float4 v = *(const float4*)&Qg[(size_t)(q0 + lr) * HIDDEN + d];
        Qs[(d + 0) * SROW + lr] = v.x * 0.125f;
        Qs[(d + 1) * SROW + lr] = v.y * 0.125f;
        Qs[(d + 2) * SROW + lr] = v.z * 0.125f;
        Qs[(d + 3) * SROW + lr] = v.w * 0.125f;
    }

    float o[4][4];
#pragma unroll
    for (int i = 0; i < 4; i++)
#pragma unroll
        for (int j = 0; j < 4; j++) o[i][j] = 0.0f;
    float m_i[4] = {-CUDART_INF_F, -CUDART_INF_F, -CUDART_INF_F, -CUDART_INF_F};
    float l_i[4] = {0.0f, 0.0f, 0.0f, 0.0f};

    for (int kt = 0; kt < SEQ; kt += 64) {
        float4 kreg[4], vreg[4];
#pragma unroll
        for (int u = 0; u < 4; u++) {
            int d = lc + (u << 2);
            kreg[u] = *(const float4*)&Kg[(size_t)(kt + lr) * HIDDEN + d];
            vreg[u] = *(const float4*)&Vg[(size_t)(kt + lr) * HIDDEN + d];
        }
        __syncthreads();
#pragma unroll
        for (int u = 0; u < 4; u++) {
            int d = lc + (u << 2);
            Ks[(d + 0) * SROW + lr] = kreg[u].x;
            Ks[(d + 1) * SROW + lr] = kreg[u].y;
            Ks[(d + 2) * SROW + lr] = kreg[u].z;
            Ks[(d + 3) * SROW + lr] = kreg[u].w;
            *(float4*)&Vs[lr * SROW + d] = vreg[u];
        }
        __syncthreads();

        float s[4][4];
#pragma unroll
        for (int i = 0; i < 4; i++)
#pragma unroll
            for (int j = 0; j < 4; j++) s[i][j] = 0.0f;
#pragma unroll 16
        for (int kk = 0; kk < 64; kk++) {
            float4 a  = *(const float4*)&Qs[kk * SROW + (ty << 2)];
            float4 bb = *(const float4*)&Ks[kk * SROW + (tx << 2)];
            float av[4] = {a.x, a.y, a.z, a.w};
            float bv[4] = {bb.x, bb.y, bb.z, bb.w};
#pragma unroll
            for (int i = 0; i < 4; i++)
#pragma unroll
                for (int j = 0; j < 4; j++)
                    s[i][j] = fmaf(av[i], bv[j], s[i][j]);
        }

#pragma unroll
        for (int i = 0; i < 4; i++) {
            float tm = fmaxf(fmaxf(s[i][0], s[i][1]), fmaxf(s[i][2], s[i][3]));
            tm = fmaxf(tm, __shfl_xor_sync(0xffffffffu, tm, 8, 16));
            tm = fmaxf(tm, __shfl_xor_sync(0xffffffffu, tm, 4, 16));
            tm = fmaxf(tm, __shfl_xor_sync(0xffffffffu, tm, 2, 16));
            tm = fmaxf(tm, __shfl_xor_sync(0xffffffffu, tm, 1, 16));
            float mnew  = fmaxf(m_i[i], tm);
            float alpha = __expf(m_i[i] - mnew);
            float ps = 0.0f;
#pragma unroll
            for (int j = 0; j < 4; j++) {
                s[i][j] = __expf(s[i][j] - mnew);
                ps += s[i][j];
            }
            ps += __shfl_xor_sync(0xffffffffu, ps, 8, 16);
            ps += __shfl_xor_sync(0xffffffffu, ps, 4, 16);
            ps += __shfl_xor_sync(0xffffffffu, ps, 2, 16);
            ps += __shfl_xor_sync(0xffffffffu, ps, 1, 16);
            l_i[i] = l_i[i] * alpha + ps;
            m_i[i] = mnew;
#pragma unroll
            for (int j = 0; j < 4; j++) o[i][j] *= alpha;
        }

#pragma unroll
        for (int j = 0; j < 4; j++)
#pragma unroll
            for (int i = 0; i < 4; i++)
                Ps[((tx << 2) + j) * SROW + (ty << 2) + i] = s[i][j];
        __syncthreads();

#pragma unroll 16
        for (int c = 0; c < 64; c++) {
            float4 a  = *(const float4*)&Ps[c * SROW + (ty << 2)];
            float4 bb = *(const float4*)&Vs[c * SROW + (tx << 2)];
            float av[4] = {a.x, a.y, a.z, a.w};
            float bv[4] = {bb.x, bb.y, bb.z, bb.w};
#pragma unroll
            for (int i = 0; i < 4; i++)
#pragma unroll
                for (int j = 0; j < 4; j++)
                    o[i][j] = fmaf(av[i], bv[j], o[i][j]);
        }
    }

    float* Og = g_ctx + (size_t)b * SEQ * HIDDEN + h * DH;
#pragma unroll
    for (int i = 0; i < 4; i++) {
        float inv = 1.0f / l_i[i];
        float4 r = make_float4(o[i][0] * inv, o[i][1] * inv, o[i][2] * inv, o[i][3] * inv);
        *(float4*)&Og[(size_t)(q0 + (ty << 2) + i) * HIDDEN + (tx << 2)] = r;
    }
}

// ---------------------------------------------------------------------------
extern "C" void kernel_launch(void* const* d_in, const int* in_sizes, int n_in,
                              void* d_out, int out_size)
{
    const float* x  = (const float*)d_in[0];
    const float* wq = (const float*)d_in[1];
    const float* wk = (const float*)d_in[2];
    const float* wv = (const float*)d_in[3];
    const float* wo = (const float*)d_in[4];
    float* out = (float*)d_out;

    cudaFuncSetAttribute(attn_kernel, cudaFuncAttributeMaxDynamicSharedMemorySize,
                         ATTN_SMEM);

    __nv_bfloat16 *xhi, *xlo, *chi, *clo, *whi, *wlo;
    cudaGetSymbolAddress((void**)&xhi, g_xhi);
    cudaGetSymbolAddress((void**)&xlo, g_xlo);
    cudaGetSymbolAddress((void**)&chi, g_chi);
    cudaGetSymbolAddress((void**)&clo, g_clo);
    cudaGetSymbolAddress((void**)&whi, g_whi);
    cudaGetSymbolAddress((void**)&wlo, g_wlo);
    float* ctx;
    cudaGetSymbolAddress((void**)&ctx, g_ctx);

    const int nx4 = MTOT * HIDDEN / 4;
    const int nw4 = HIDDEN * HIDDEN / 4;
    const size_t wstep = (size_t)HIDDEN * HIDDEN;

    // 1) split inputs to bf16 hi/lo
    split_kernel<<<(nx4 + 255) / 256, 256>>>(x, xhi, xlo, nx4);
    split_kernel<<<(nw4 + 255) / 256, 256>>>(wq, whi + 0 * wstep, wlo + 0 * wstep, nw4);
    split_kernel<<<(nw4 + 255) / 256, 256>>>(wk, whi + 1 * wstep, wlo + 1 * wstep, nw4);
    split_kernel<<<(nw4 + 255) / 256, 256>>>(wv, whi + 2 * wstep, wlo + 2 * wstep, nw4);
    split_kernel<<<(nw4 + 255) / 256, 256>>>(wo, whi + 3 * wstep, wlo + 3 * wstep, nw4);

    // 2) QKV projections (HMMA)
    dim3 gqkv(HIDDEN / 128, MTOT / 128, 3);    // (6, 64, 3)
    qkv_mma_kernel<<<gqkv, 256>>>();

    // 3) attention (SIMT fp32)
    dim3 gattn(SEQ / 64, BATCH * NH);          // (32, 48)
    attn_kernel<<<gattn, 256, ATTN_SMEM>>>();

    // 4) split context, O-projection (HMMA)
    split_kernel<<<(nx4 + 255) / 256, 256>>>(ctx, chi, clo, nx4);
    dim3 gproj(HIDDEN / 128, MTOT / 128);      // (6, 64)
    proj_mma_kernel<<<gproj, 256>>>(out);
}

// round 4
// speedup vs baseline: 2.9539x; 2.1440x over previous
#include <cuda_runtime.h>
#include <cuda_bf16.h>
#include <math_constants.h>
#include <cstdint>

#define HIDDEN 768
#define NH     12
#define DH     64
#define BATCH  4
#define SEQ    2048
#define MTOT   (BATCH*SEQ)   // 8192

// ---------------------------------------------------------------------------
// Scratch (__device__ globals)
// ---------------------------------------------------------------------------
__device__ __nv_bfloat16 g_xhi[(size_t)MTOT * HIDDEN];
__device__ __nv_bfloat16 g_xlo[(size_t)MTOT * HIDDEN];
__device__ __nv_bfloat16 g_whi[4][(size_t)HIDDEN * HIDDEN];
__device__ __nv_bfloat16 g_wlo[4][(size_t)HIDDEN * HIDDEN];
__device__ __nv_bfloat16 g_qhi[(size_t)MTOT * HIDDEN];
__device__ __nv_bfloat16 g_qlo[(size_t)MTOT * HIDDEN];
__device__ __nv_bfloat16 g_khi[(size_t)MTOT * HIDDEN];
__device__ __nv_bfloat16 g_klo[(size_t)MTOT * HIDDEN];
__device__ __nv_bfloat16 g_vhi[(size_t)MTOT * HIDDEN];
__device__ __nv_bfloat16 g_vlo[(size_t)MTOT * HIDDEN];
__device__ __nv_bfloat16 g_chi[(size_t)MTOT * HIDDEN];
__device__ __nv_bfloat16 g_clo[(size_t)MTOT * HIDDEN];

// ---------------------------------------------------------------------------
// Warp-MMA primitives (baseline PTX, valid on compute_103)
// ---------------------------------------------------------------------------
__device__ __forceinline__ uint32_t smem_u32(const void* p) {
    uint32_t a;
    asm("{ .reg .u64 t; cvta.to.shared.u64 t, %1; cvt.u32.u64 %0, t; }"
        : "=r"(a) : "l"(p));
    return a;
}

__device__ __forceinline__ void mma_bf16(float* d, const uint32_t* a, const uint32_t* b) {
    asm volatile(
        "mma.sync.aligned.m16n8k16.row.col.f32.bf16.bf16.f32 "
        "{%0,%1,%2,%3}, {%4,%5,%6,%7}, {%8,%9}, {%0,%1,%2,%3};"
        : "+f"(d[0]), "+f"(d[1]), "+f"(d[2]), "+f"(d[3])
        : "r"(a[0]), "r"(a[1]), "r"(a[2]), "r"(a[3]), "r"(b[0]), "r"(b[1]));
}

__device__ __forceinline__ void ldsm_x4(uint32_t* r, uint32_t addr) {
    asm volatile("ldmatrix.sync.aligned.m8n8.x4.shared.b16 {%0,%1,%2,%3}, [%4];"
                 : "=r"(r[0]), "=r"(r[1]), "=r"(r[2]), "=r"(r[3]) : "r"(addr));
}
__device__ __forceinline__ void ldsm_x2(uint32_t* r, uint32_t addr) {
    asm volatile("ldmatrix.sync.aligned.m8n8.x2.shared.b16 {%0,%1}, [%2];"
                 : "=r"(r[0]), "=r"(r[1]) : "r"(addr));
}
__device__ __forceinline__ void ldsm_x2_t(uint32_t* r, uint32_t addr) {
    asm volatile("ldmatrix.sync.aligned.m8n8.x2.trans.shared.b16 {%0,%1}, [%2];"
                 : "=r"(r[0]), "=r"(r[1]) : "r"(addr));
}

__device__ __forceinline__ uint32_t bfpack(__nv_bfloat16 a, __nv_bfloat16 b) {
    __nv_bfloat162 t; t.x = a; t.y = b;
    return *(uint32_t*)&t;
}
__device__ __forceinline__ void split2(float a, float b, uint32_t& hi, uint32_t& lo) {
    __nv_bfloat16 ha = __float2bfloat16(a), hb = __float2bfloat16(b);
    __nv_bfloat16 la = __float2bfloat16(a - __bfloat162float(ha));
    __nv_bfloat16 lb = __float2bfloat16(b - __bfloat162float(hb));
    hi = bfpack(ha, hb);
    lo = bfpack(la, lb);
}

// ---------------------------------------------------------------------------
// fp32 -> bf16 hi/lo split kernel (inputs + weights)
// ---------------------------------------------------------------------------
__global__ __launch_bounds__(256) void split_kernel(const float* __restrict__ src,
                                                    __nv_bfloat16* __restrict__ hi,
                                                    __nv_bfloat16* __restrict__ lo,
                                                    int n4)
{
    int i = blockIdx.x * blockDim.x + threadIdx.x;
    if (i >= n4) return;
    float4 v = ((const float4*)src)[i];
    uint32_t h0, l0, h1, l1;
    split2(v.x, v.y, h0, l0);
    split2(v.z, v.w, h1, l1);
    ((uint32_t*)hi)[2 * i + 0] = h0;
    ((uint32_t*)hi)[2 * i + 1] = h1;
    ((uint32_t*)lo)[2 * i + 0] = l0;
    ((uint32_t*)lo)[2 * i + 1] = l1;
}

// ---------------------------------------------------------------------------
// HMMA bf16-split GEMM core: acc[4][4][4] = A[M,K] @ B[N,K]^T  (K=768)
// 128x128 CTA, BK=32, 8 warps (2x4), warp tile 64x32.
// ---------------------------------------------------------------------------
#define KCH (HIDDEN / 32)    // 24

struct GemmFrag {
    float acc[4][4][4];
    int lane, wm, wn;
};

__device__ __forceinline__ void hmma_core(const __nv_bfloat16* __restrict__ Ahi,
                                          const __nv_bfloat16* __restrict__ Alo,
                                          const __nv_bfloat16* __restrict__ Bhi,
                                          const __nv_bfloat16* __restrict__ Blo,
                                          int bm, int bn, GemmFrag& fr)
{
    __shared__ uint4 sAh[512], sAl[512], sBh[512], sBl[512];

    const int tid  = threadIdx.x;
    const int lane = tid & 31;
    const int wid  = tid >> 5;
    fr.lane = lane;
    fr.wm   = (wid & 1) * 64;
    fr.wn   = (wid >> 1) * 32;

    const int r0 = tid >> 2;
    const int c0 = tid & 3;
    const int dst0 = r0 * 4 + (c0 ^ ((r0 >> 1) & 3));
    const int dst1 = dst0 + 256;

    const uint4* Ah4 = (const uint4*)Ahi;
    const uint4* Al4 = (const uint4*)Alo;
    const uint4* Bh4 = (const uint4*)Bhi;
    const uint4* Bl4 = (const uint4*)Blo;
    const int rowstride4 = HIDDEN / 8;
    const size_t srcA0 = (size_t)(bm + r0) * rowstride4 + c0;
    const size_t srcA1 = (size_t)(bm + r0 + 64) * rowstride4 + c0;
    const size_t srcB0 = (size_t)(bn + r0) * rowstride4 + c0;
    const size_t srcB1 = (size_t)(bn + r0 + 64) * rowstride4 + c0;

    const uint32_t bAh = smem_u32(sAh);
    const uint32_t bAl = smem_u32(sAl);
    const uint32_t bBh = smem_u32(sBh);
    const uint32_t bBl = smem_u32(sBl);

    uint32_t offA[2][4], offB[2][4];
#pragma unroll
    for (int mi = 0; mi < 4; mi++) {
        int rowA = fr.wm + mi * 16 + (lane & 15);
        int keyA = (rowA >> 1) & 3;
#pragma unroll
        for (int ks = 0; ks < 2; ks++) {
            int c = ks * 2 + (lane >> 4);
            offA[ks][mi] = rowA * 64 + ((c ^ keyA) << 4);
        }
    }
#pragma unroll
    for (int ni = 0; ni < 4; ni++) {
        int rowB = fr.wn + ni * 8 + (lane & 7);
        int keyB = (rowB >> 1) & 3;
#pragma unroll
        for (int ks = 0; ks < 2; ks++) {
            int c = ks * 2 + ((lane >> 3) & 1);
            offB[ks][ni] = rowB * 64 + ((c ^ keyB) << 4);
        }
    }

#pragma unroll
    for (int mi = 0; mi < 4; mi++)
#pragma unroll
        for (int ni = 0; ni < 4; ni++)
#pragma unroll
            for (int t = 0; t < 4; t++) fr.acc[mi][ni][t] = 0.0f;

    for (int kc = 0; kc < KCH; kc++) {
        const size_t ko = (size_t)kc * 4;
        uint4 vah0 = Ah4[srcA0 + ko], vah1 = Ah4[srcA1 + ko];
        uint4 val0 = Al4[srcA0 + ko], val1 = Al4[srcA1 + ko];
        uint4 vbh0 = Bh4[srcB0 + ko], vbh1 = Bh4[srcB1 + ko];
        uint4 vbl0 = Bl4[srcB0 + ko], vbl1 = Bl4[srcB1 + ko];
        __syncthreads();
        sAh[dst0] = vah0; sAh[dst1] = vah1;
        sAl[dst0] = val0; sAl[dst1] = val1;
        sBh[dst0] = vbh0; sBh[dst1] = vbh1;
        sBl[dst0] = vbl0; sBl[dst1] = vbl1;
        __syncthreads();

#pragma unroll
        for (int ks = 0; ks < 2; ks++) {
            uint32_t ah[4][4], al[4][4], bh[4][2], bl[4][2];
#pragma unroll
            for (int mi = 0; mi < 4; mi++) {
                ldsm_x4(ah[mi], bAh + offA[ks][mi]);
                ldsm_x4(al[mi], bAl + offA[ks][mi]);
            }
#pragma unroll
            for (int ni = 0; ni < 4; ni++) {
                ldsm_x2(bh[ni], bBh + offB[ks][ni]);
                ldsm_x2(bl[ni], bBl + offB[ks][ni]);
            }
#pragma unroll
            for (int mi = 0; mi < 4; mi++)
#pragma unroll
                for (int ni = 0; ni < 4; ni++) {
                    mma_bf16(fr.acc[mi][ni], ah[mi], bh[ni]);
                    mma_bf16(fr.acc[mi][ni], ah[mi], bl[ni]);
                    mma_bf16(fr.acc[mi][ni], al[mi], bh[ni]);
                }
        }
    }
}

// qkv: epilogue writes bf16 hi/lo (optionally scaled)
__global__ __launch_bounds__(256) void qkv_mma_kernel()
{
    const int z = blockIdx.z;
    __nv_bfloat16 *Ohi, *Olo;
    float scale;
    if (z == 0)      { Ohi = g_qhi; Olo = g_qlo; scale = 0.125f; }
    else if (z == 1) { Ohi = g_khi; Olo = g_klo; scale = 1.0f; }
    else             { Ohi = g_vhi; Olo = g_vlo; scale = 1.0f; }

    GemmFrag fr;
    hmma_core(g_xhi, g_xlo, g_whi[z], g_wlo[z], blockIdx.y * 128, blockIdx.x * 128, fr);

    const int bm = blockIdx.y * 128, bn = blockIdx.x * 128;
#pragma unroll
    for (int mi = 0; mi < 4; mi++) {
        int row = bm + fr.wm + mi * 16 + (fr.lane >> 2);
#pragma unroll
        for (int ni = 0; ni < 4; ni++) {
            int col = bn + fr.wn + ni * 8 + ((fr.lane & 3) << 1);
            uint32_t h0, l0, h1, l1;
            split2(fr.acc[mi][ni][0] * scale, fr.acc[mi][ni][1] * scale, h0, l0);
            split2(fr.acc[mi][ni][2] * scale, fr.acc[mi][ni][3] * scale, h1, l1);
            *(uint32_t*)(Ohi + (size_t)row * HIDDEN + col) = h0;
            *(uint32_t*)(Olo + (size_t)row * HIDDEN + col) = l0;
            *(uint32_t*)(Ohi + (size_t)(row + 8) * HIDDEN + col) = h1;
            *(uint32_t*)(Olo + (size_t)(row + 8) * HIDDEN + col) = l1;
        }
    }
}

// proj: fp32 out
__global__ __launch_bounds__(256) void proj_mma_kernel(float* __restrict__ out)
{
    GemmFrag fr;
    hmma_core(g_chi, g_clo, g_whi[3], g_wlo[3], blockIdx.y * 128, blockIdx.x * 128, fr);

    const int bm = blockIdx.y * 128, bn = blockIdx.x * 128;
#pragma unroll
    for (int mi = 0; mi < 4; mi++) {
        int row = bm + fr.wm + mi * 16 + (fr.lane >> 2);
#pragma unroll
        for (int ni = 0; ni < 4; ni++) {
            int col = bn + fr.wn + ni * 8 + ((fr.lane & 3) << 1);
            *(float2*)(out + (size_t)row * HIDDEN + col) =
                make_float2(fr.acc[mi][ni][0], fr.acc[mi][ni][1]);
            *(float2*)(out + (size_t)(row + 8) * HIDDEN + col) =
                make_float2(fr.acc[mi][ni][2], fr.acc[mi][ni][3]);
        }
    }
}

// ---------------------------------------------------------------------------
// Tensor-core flash attention.
// CTA: 128 queries x one (b,h). 8 warps x 16 q-rows. Key tiles of 64.
// smem: 32KB (union: Q staging / per-iter K,V hi/lo tiles), swizzle c^(r&7).
// ---------------------------------------------------------------------------
__global__ __launch_bounds__(256) void attn_mma_kernel()
{
    __shared__ uint4 sm4[2048];          // 32 KB
    const uint32_t sb = smem_u32(sm4);

    const int tid  = threadIdx.x;
    const int lane = tid & 31;
    const int wid  = tid >> 5;
    const int bh   = blockIdx.y;
    const int b    = bh / NH;
    const int h    = bh % NH;
    const int q0   = blockIdx.x * 128;

    const size_t base = (size_t)b * SEQ * HIDDEN + h * DH;

    // ---- stage Q (hi at chunks 0..1023, lo at 1024..2047) ----
    {
#pragma unroll
        for (int j = 0; j < 4; j++) {
            int idx = j * 256 + tid;
            int r = idx >> 3, c = idx & 7;
            int d = r * 8 + (c ^ (r & 7));
            const uint4* qh = (const uint4*)(g_qhi + base + (size_t)(q0 + r) * HIDDEN);
            const uint4* ql = (const uint4*)(g_qlo + base + (size_t)(q0 + r) * HIDDEN);
            sm4[d]        = qh[c];
            sm4[1024 + d] = ql[c];
        }
    }
    __syncthreads();

    // ---- Q fragments (held for whole kernel) ----
    uint32_t qh[4][4], ql[4][4];
    {
        int qrow = wid * 16 + (lane & 15);
        int key  = qrow & 7;
#pragma unroll
        for (int ks = 0; ks < 4; ks++) {
            int c = ks * 2 + (lane >> 4);
            uint32_t off = (uint32_t)(qrow * 8 + (c ^ key)) * 16;
            ldsm_x4(qh[ks], sb + off);
            ldsm_x4(ql[ks], sb + 16384 + off);
        }
    }
    __syncthreads();

    float accO[8][4];
#pragma unroll
    for (int n = 0; n < 8; n++)
#pragma unroll
        for (int t = 0; t < 4; t++) accO[n][t] = 0.0f;
    float m0 = -CUDART_INF_F, m1 = -CUDART_INF_F, l0 = 0.0f, l1 = 0.0f;

    // staging indices for K/V tiles (64 rows x 8 chunks per array)
    const int sr = tid >> 3;           // 0..31
    const int sc = tid & 7;

    for (int kt = 0; kt < SEQ; kt += 64) {
        // ---- load K/V hi/lo tiles to regs, then swap into smem ----
        uint4 vk[8];
        {
            const uint4* p0h = (const uint4*)(g_khi + base + (size_t)(kt + sr) * HIDDEN);
            const uint4* p1h = (const uint4*)(g_khi + base + (size_t)(kt + 32 + sr) * HIDDEN);
            const uint4* p0l = (const uint4*)(g_klo + base + (size_t)(kt + sr) * HIDDEN);
            const uint4* p1l = (const uint4*)(g_klo + base + (size_t)(kt + 32 + sr) * HIDDEN);
            const uint4* q0h = (const uint4*)(g_vhi + base + (size_t)(kt + sr) * HIDDEN);
            const uint4* q1h = (const uint4*)(g_vhi + base + (size_t)(kt + 32 + sr) * HIDDEN);
            const uint4* q0l = (const uint4*)(g_vlo + base + (size_t)(kt + sr) * HIDDEN);
            const uint4* q1l = (const uint4*)(g_vlo + base + (size_t)(kt + 32 + sr) * HIDDEN);
            vk[0] = p0h[sc]; vk[1] = p1h[sc];
            vk[2] = p0l[sc]; vk[3] = p1l[sc];
            vk[4] = q0h[sc]; vk[5] = q1h[sc];
            vk[6] = q0l[sc]; vk[7] = q1l[sc];
        }
        __syncthreads();
        {
            int d0 = sr * 8 + (sc ^ (sr & 7));
            int d1 = (sr + 32) * 8 + (sc ^ (sr & 7));
            sm4[d0]        = vk[0]; sm4[d1]        = vk[1];   // Khi: 0..511
            sm4[512 + d0]  = vk[2]; sm4[512 + d1]  = vk[3];   // Klo
            sm4[1024 + d0] = vk[4]; sm4[1024 + d1] = vk[5];   // Vhi
            sm4[1536 + d0] = vk[6]; sm4[1536 + d1] = vk[7];   // Vlo
        }
        __syncthreads();

        // ---- S = Q.K^T (3-term) ----
        float s[8][4];
#pragma unroll
        for (int n = 0; n < 8; n++)
#pragma unroll
            for (int t = 0; t < 4; t++) s[n][t] = 0.0f;

#pragma unroll
        for (int ks = 0; ks < 4; ks++) {
#pragma unroll
            for (int ni = 0; ni < 8; ni++) {
                int krow = ni * 8 + (lane & 7);
                int c = ks * 2 + ((lane >> 3) & 1);
                uint32_t off = (uint32_t)(krow * 8 + (c ^ (krow & 7))) * 16;
                uint32_t kh2[2], kl2[2];
                ldsm_x2(kh2, sb + off);
                ldsm_x2(kl2, sb + 8192 + off);
                mma_bf16(s[ni], qh[ks], kh2);
                mma_bf16(s[ni], qh[ks], kl2);
                mma_bf16(s[ni], ql[ks], kh2);
            }
        }

        // ---- online softmax (rows r = lane>>2 and r+8) ----
        float rmax0 = -CUDART_INF_F, rmax1 = -CUDART_INF_F;
#pragma unroll
        for (int n = 0; n < 8; n++) {
            rmax0 = fmaxf(rmax0, fmaxf(s[n][0], s[n][1]));
            rmax1 = fmaxf(rmax1, fmaxf(s[n][2], s[n][3]));
        }
        rmax0 = fmaxf(rmax0, __shfl_xor_sync(0xffffffffu, rmax0, 1));
        rmax0 = fmaxf(rmax0, __shfl_xor_sync(0xffffffffu, rmax0, 2));
        rmax1 = fmaxf(rmax1, __shfl_xor_sync(0xffffffffu, rmax1, 1));
        rmax1 = fmaxf(rmax1, __shfl_xor_sync(0xffffffffu, rmax1, 2));
        float mn0 = fmaxf(m0, rmax0), mn1 = fmaxf(m1, rmax1);
        float a0 = __expf(m0 - mn0), a1 = __expf(m1 - mn1);
        float sum0 = 0.0f, sum1 = 0.0f;
#pragma unroll
        for (int n = 0; n < 8; n++) {
            s[n][0] = __expf(s[n][0] - mn0);
            s[n][1] = __expf(s[n][1] - mn0);
            s[n][2] = __expf(s[n][2] - mn1);
            s[n][3] = __expf(s[n][3] - mn1);
            sum0 += s[n][0] + s[n][1];
            sum1 += s[n][2] + s[n][3];
        }
        sum0 += __shfl_xor_sync(0xffffffffu, sum0, 1);
        sum0 += __shfl_xor_sync(0xffffffffu, sum0, 2);
        sum1 += __shfl_xor_sync(0xffffffffu, sum1, 1);
        sum1 += __shfl_xor_sync(0xffffffffu, sum1, 2);
        l0 = l0 * a0 + sum0;
        l1 = l1 * a1 + sum1;
        m0 = mn0; m1 = mn1;
#pragma unroll
        for (int n = 0; n < 8; n++) {
            accO[n][0] *= a0; accO[n][1] *= a0;
            accO[n][2] *= a1; accO[n][3] *= a1;
        }

        // ---- pack P into A fragments (hi/lo) ----
        uint32_t ph[4][4], pl[4][4];
#pragma unroll
        for (int j = 0; j < 4; j++) {
            split2(s[2 * j][0],     s[2 * j][1],     ph[j][0], pl[j][0]);
            split2(s[2 * j][2],     s[2 * j][3],     ph[j][1], pl[j][1]);
            split2(s[2 * j + 1][0], s[2 * j + 1][1], ph[j][2], pl[j][2]);
            split2(s[2 * j + 1][2], s[2 * j + 1][3], ph[j][3], pl[j][3]);
        }

        // ---- O += P.V (3-term), V via ldmatrix.trans ----
#pragma unroll
        for (int j = 0; j < 4; j++) {
#pragma unroll
            for (int n2 = 0; n2 < 8; n2++) {
                int vrow = j * 16 + (lane & 15);
                uint32_t off = (uint32_t)(vrow * 8 + (n2 ^ (vrow & 7))) * 16;
                uint32_t vh2[2], vl2[2];
                ldsm_x2_t(vh2, sb + 16384 + off);
                ldsm_x2_t(vl2, sb + 24576 + off);
                mma_bf16(accO[n2], ph[j], vh2);
                mma_bf16(accO[n2], ph[j], vl2);
                mma_bf16(accO[n2], pl[j], vh2);
            }
        }
    }

    // ---- epilogue: normalize, write ctx hi/lo bf16 ----
    float inv0 = 1.0f / l0, inv1 = 1.0f / l1;
    int row = q0 + wid * 16 + (lane >> 2);
#pragma unroll
    for (int n2 = 0; n2 < 8; n2++) {
        int col = n2 * 8 + ((lane & 3) << 1);
        uint32_t h0, lo0, h1, lo1;
        split2(accO[n2][0] * inv0, accO[n2][1] * inv0, h0, lo0);
        split2(accO[n2][2] * inv1, accO[n2][3] * inv1, h1, lo1);
        size_t p0 = base + (size_t)row * HIDDEN + col;
        size_t p1 = base + (size_t)(row + 8) * HIDDEN + col;
        *(uint32_t*)(g_chi + p0) = h0;
        *(uint32_t*)(g_clo + p0) = lo0;
        *(uint32_t*)(g_chi + p1) = h1;
        *(uint32_t*)(g_clo + p1) = lo1;
    }
}

// ---------------------------------------------------------------------------
extern "C" void kernel_launch(void* const* d_in, const int* in_sizes, int n_in,
                              void* d_out, int out_size)
{
    const float* x  = (const float*)d_in[0];
    const float* wq = (const float*)d_in[1];
    const float* wk = (const float*)d_in[2];
    const float* wv = (const float*)d_in[3];
    const float* wo = (const float*)d_in[4];
    float* out = (float*)d_out;

    __nv_bfloat16 *xhi, *xlo, *whi, *wlo;
    cudaGetSymbolAddress((void**)&xhi, g_xhi);
    cudaGetSymbolAddress((void**)&xlo, g_xlo);
    cudaGetSymbolAddress((void**)&whi, g_whi);
    cudaGetSymbolAddress((void**)&wlo, g_wlo);

    const int nx4 = MTOT * HIDDEN / 4;
    const int nw4 = HIDDEN * HIDDEN / 4;
    const size_t wstep = (size_t)HIDDEN * HIDDEN;

    split_kernel<<<(nx4 + 255) / 256, 256>>>(x, xhi, xlo, nx4);
    split_kernel<<<(nw4 + 255) / 256, 256>>>(wq, whi + 0 * wstep, wlo + 0 * wstep, nw4);
    split_kernel<<<(nw4 + 255) / 256, 256>>>(wk, whi + 1 * wstep, wlo + 1 * wstep, nw4);
    split_kernel<<<(nw4 + 255) / 256, 256>>>(wv, whi + 2 * wstep, wlo + 2 * wstep, nw4);
    split_kernel<<<(nw4 + 255) / 256, 256>>>(wo, whi + 3 * wstep, wlo + 3 * wstep, nw4);

    dim3 gqkv(HIDDEN / 128, MTOT / 128, 3);    // (6, 64, 3)
    qkv_mma_kernel<<<gqkv, 256>>>();

    dim3 gattn(SEQ / 128, BATCH * NH);         // (16, 48)
    attn_mma_kernel<<<gattn, 256>>>();

    dim3 gproj(HIDDEN / 128, MTOT / 128);      // (6, 64)
    proj_mma_kernel<<<gproj, 256>>>(out);
}

// round 5
// speedup vs baseline: 3.1429x; 1.0640x over previous
#include <cuda_runtime.h>
#include <cuda_bf16.h>
#include <math_constants.h>
#include <cstdint>

#define HIDDEN 768
#define NH     12
#define DH     64
#define BATCH  4
#define SEQ    2048
#define MTOT   (BATCH*SEQ)   // 8192

// ---------------------------------------------------------------------------
// Scratch (__device__ globals)
// ---------------------------------------------------------------------------
__device__ __nv_bfloat16 g_xhi[(size_t)MTOT * HIDDEN];
__device__ __nv_bfloat16 g_xlo[(size_t)MTOT * HIDDEN];
__device__ __nv_bfloat16 g_whi[4][(size_t)HIDDEN * HIDDEN];
__device__ __nv_bfloat16 g_wlo[4][(size_t)HIDDEN * HIDDEN];
__device__ __nv_bfloat16 g_qhi[(size_t)MTOT * HIDDEN];
__device__ __nv_bfloat16 g_qlo[(size_t)MTOT * HIDDEN];
__device__ __nv_bfloat16 g_khi[(size_t)MTOT * HIDDEN];
__device__ __nv_bfloat16 g_klo[(size_t)MTOT * HIDDEN];
__device__ __nv_bfloat16 g_vhi[(size_t)MTOT * HIDDEN];
__device__ __nv_bfloat16 g_vlo[(size_t)MTOT * HIDDEN];
__device__ __nv_bfloat16 g_chi[(size_t)MTOT * HIDDEN];
__device__ __nv_bfloat16 g_clo[(size_t)MTOT * HIDDEN];

// ---------------------------------------------------------------------------
// PTX primitives (baseline PTX only — valid on compute_103 target)
// ---------------------------------------------------------------------------
__device__ __forceinline__ uint32_t smem_u32(const void* p) {
    uint32_t a;
    asm("{ .reg .u64 t; cvta.to.shared.u64 t, %1; cvt.u32.u64 %0, t; }"
        : "=r"(a) : "l"(p));
    return a;
}

__device__ __forceinline__ void mma_bf16(float* d, const uint32_t* a, const uint32_t* b) {
    asm volatile(
        "mma.sync.aligned.m16n8k16.row.col.f32.bf16.bf16.f32 "
        "{%0,%1,%2,%3}, {%4,%5,%6,%7}, {%8,%9}, {%0,%1,%2,%3};"
        : "+f"(d[0]), "+f"(d[1]), "+f"(d[2]), "+f"(d[3])
        : "r"(a[0]), "r"(a[1]), "r"(a[2]), "r"(a[3]), "r"(b[0]), "r"(b[1]));
}

__device__ __forceinline__ void ldsm_x4(uint32_t* r, uint32_t addr) {
    asm volatile("ldmatrix.sync.aligned.m8n8.x4.shared.b16 {%0,%1,%2,%3}, [%4];"
                 : "=r"(r[0]), "=r"(r[1]), "=r"(r[2]), "=r"(r[3]) : "r"(addr));
}
__device__ __forceinline__ void ldsm_x4_t(uint32_t* r, uint32_t addr) {
    asm volatile("ldmatrix.sync.aligned.m8n8.x4.trans.shared.b16 {%0,%1,%2,%3}, [%4];"
                 : "=r"(r[0]), "=r"(r[1]), "=r"(r[2]), "=r"(r[3]) : "r"(addr));
}

__device__ __forceinline__ void cp_async16(uint32_t dst, const void* src) {
    asm volatile(
        "{ .reg .u64 g; cvta.to.global.u64 g, %1; "
        "cp.async.cg.shared.global [%0], [g], 16; }"
        :: "r"(dst), "l"(src));
}
#define CP_COMMIT() asm volatile("cp.async.commit_group;" ::: "memory")
#define CP_WAIT(n)  asm volatile("cp.async.wait_group %0;" :: "n"(n) : "memory")

__device__ __forceinline__ uint32_t bfpack(__nv_bfloat16 a, __nv_bfloat16 b) {
    __nv_bfloat162 t; t.x = a; t.y = b;
    return *(uint32_t*)&t;
}
__device__ __forceinline__ void split2(float a, float b, uint32_t& hi, uint32_t& lo) {
    __nv_bfloat16 ha = __float2bfloat16(a), hb = __float2bfloat16(b);
    __nv_bfloat16 la = __float2bfloat16(a - __bfloat162float(ha));
    __nv_bfloat16 lb = __float2bfloat16(b - __bfloat162float(hb));
    hi = bfpack(ha, hb);
    lo = bfpack(la, lb);
}

// ---------------------------------------------------------------------------
// fp32 -> bf16 hi/lo split kernels
// ---------------------------------------------------------------------------
__device__ __forceinline__ void split_body(const float* __restrict__ src,
                                           __nv_bfloat16* __restrict__ hi,
                                           __nv_bfloat16* __restrict__ lo, int i)
{
    float4 v = ((const float4*)src)[i];
    uint32_t h0, l0, h1, l1;
    split2(v.x, v.y, h0, l0);
    split2(v.z, v.w, h1, l1);
    ((uint32_t*)hi)[2 * i + 0] = h0;
    ((uint32_t*)hi)[2 * i + 1] = h1;
    ((uint32_t*)lo)[2 * i + 0] = l0;
    ((uint32_t*)lo)[2 * i + 1] = l1;
}

__global__ __launch_bounds__(256) void split_x_kernel(const float* __restrict__ src)
{
    int i = blockIdx.x * blockDim.x + threadIdx.x;
    if (i < MTOT * HIDDEN / 4) split_body(src, g_xhi, g_xlo, i);
}

__global__ __launch_bounds__(256) void split_w_kernel(const float* __restrict__ w0,
                                                      const float* __restrict__ w1,
                                                      const float* __restrict__ w2,
                                                      const float* __restrict__ w3)
{
    int z = blockIdx.y;
    const float* src = (z == 0) ? w0 : (z == 1) ? w1 : (z == 2) ? w2 : w3;
    int i = blockIdx.x * blockDim.x + threadIdx.x;
    if (i < HIDDEN * HIDDEN / 4) split_body(src, g_whi[z], g_wlo[z], i);
}

// ---------------------------------------------------------------------------
// HMMA bf16-split GEMM core, cp.async double-buffered.
// 128x128 CTA, BK=32, 8 warps (2x4), warp tile 64x32. Dyn smem: 2 x 32KB.
// Buffer layout (uint4 idx, rel.): Ah 0..511, Al 512.., Bh 1024.., Bl 1536..
// ---------------------------------------------------------------------------
#define KCH (HIDDEN / 32)    // 24
#define GEMM_SMEM 65536

extern __shared__ uint4 dynsm[];

struct GemmFrag {
    float acc[4][4][4];
    int lane, wm, wn;
};

__device__ __forceinline__ void hmma_core(const __nv_bfloat16* __restrict__ Ahi,
                                          const __nv_bfloat16* __restrict__ Alo,
                                          const __nv_bfloat16* __restrict__ Bhi,
                                          const __nv_bfloat16* __restrict__ Blo,
                                          int bm, int bn, GemmFrag& fr)
{
    const uint32_t sb = smem_u32(dynsm);

    const int tid  = threadIdx.x;
    const int lane = tid & 31;
    const int wid  = tid >> 5;
    fr.lane = lane;
    fr.wm   = (wid & 1) * 64;
    fr.wn   = (wid >> 1) * 32;

    const int r0 = tid >> 2;
    const int c0 = tid & 3;
    const uint32_t dst0 = (uint32_t)(r0 * 4 + (c0 ^ ((r0 >> 1) & 3))) * 16;
    const uint32_t dst1 = dst0 + 4096;

    const uint4* Ah4 = (const uint4*)Ahi;
    const uint4* Al4 = (const uint4*)Alo;
    const uint4* Bh4 = (const uint4*)Bhi;
    const uint4* Bl4 = (const uint4*)Blo;
    const int rowstride4 = HIDDEN / 8;
    const size_t srcA0 = (size_t)(bm + r0) * rowstride4 + c0;
    const size_t srcA1 = (size_t)(bm + r0 + 64) * rowstride4 + c0;
    const size_t srcB0 = (size_t)(bn + r0) * rowstride4 + c0;
    const size_t srcB1 = (size_t)(bn + r0 + 64) * rowstride4 + c0;

    // ldmatrix offsets (byte, relative to array base)
    uint32_t offA[2][4], offB[2][2];
#pragma unroll
    for (int mi = 0; mi < 4; mi++) {
        int rowA = fr.wm + mi * 16 + (lane & 15);
        int keyA = (rowA >> 1) & 3;
#pragma unroll
        for (int ks = 0; ks < 2; ks++) {
            int c = ks * 2 + (lane >> 4);
            offA[ks][mi] = rowA * 64 + ((c ^ keyA) << 4);
        }
    }
#pragma unroll
    for (int p = 0; p < 2; p++) {       // ni pair: (2p, 2p+1)
        int rowB = fr.wn + (2 * p + ((lane >> 4) & 1)) * 8 + (lane & 7);
        int keyB = (rowB >> 1) & 3;
#pragma unroll
        for (int ks = 0; ks < 2; ks++) {
            int c = ks * 2 + ((lane >> 3) & 1);
            offB[ks][p] = rowB * 64 + ((c ^ keyB) << 4);
        }
    }

#pragma unroll
    for (int mi = 0; mi < 4; mi++)
#pragma unroll
        for (int ni = 0; ni < 4; ni++)
#pragma unroll
            for (int t = 0; t < 4; t++) fr.acc[mi][ni][t] = 0.0f;

    auto stage = [&](int kc, int buf) {
        const size_t ko = (size_t)kc * 4;
        uint32_t d = sb + (uint32_t)buf * 32768;
        cp_async16(d + dst0,         Ah4 + srcA0 + ko);
        cp_async16(d + dst1,         Ah4 + srcA1 + ko);
        cp_async16(d + 8192 + dst0,  Al4 + srcA0 + ko);
        cp_async16(d + 8192 + dst1,  Al4 + srcA1 + ko);
        cp_async16(d + 16384 + dst0, Bh4 + srcB0 + ko);
        cp_async16(d + 16384 + dst1, Bh4 + srcB1 + ko);
        cp_async16(d + 24576 + dst0, Bl4 + srcB0 + ko);
        cp_async16(d + 24576 + dst1, Bl4 + srcB1 + ko);
    };

    stage(0, 0);
    CP_COMMIT();

    for (int kc = 0; kc < KCH; kc++) {
        if (kc + 1 < KCH) {
            stage(kc + 1, (kc + 1) & 1);
            CP_COMMIT();
            CP_WAIT(1);
        } else {
            CP_WAIT(0);
        }
        __syncthreads();

        const uint32_t bAh = sb + (uint32_t)(kc & 1) * 32768;
        const uint32_t bAl = bAh + 8192;
        const uint32_t bBh = bAh + 16384;
        const uint32_t bBl = bAh + 24576;

#pragma unroll
        for (int ks = 0; ks < 2; ks++) {
            uint32_t ah[4][4], al[4][4], bh[2][4], bl[2][4];
#pragma unroll
            for (int mi = 0; mi < 4; mi++) {
                ldsm_x4(ah[mi], bAh + offA[ks][mi]);
                ldsm_x4(al[mi], bAl + offA[ks][mi]);
            }
#pragma unroll
            for (int p = 0; p < 2; p++) {
                ldsm_x4(bh[p], bBh + offB[ks][p]);
                ldsm_x4(bl[p], bBl + offB[ks][p]);
            }
#pragma unroll
            for (int mi = 0; mi < 4; mi++)
#pragma unroll
                for (int ni = 0; ni < 4; ni++) {
                    const uint32_t* bhf = &bh[ni >> 1][(ni & 1) * 2];
                    const uint32_t* blf = &bl[ni >> 1][(ni & 1) * 2];
                    mma_bf16(fr.acc[mi][ni], ah[mi], bhf);
                    mma_bf16(fr.acc[mi][ni], ah[mi], blf);
                    mma_bf16(fr.acc[mi][ni], al[mi], bhf);
                }
        }
        __syncthreads();
    }
}

// qkv: epilogue writes bf16 hi/lo (Q pre-scaled by 1/8)
__global__ __launch_bounds__(256) void qkv_mma_kernel()
{
    const int z = blockIdx.z;
    __nv_bfloat16 *Ohi, *Olo;
    float scale;
    if (z == 0)      { Ohi = g_qhi; Olo = g_qlo; scale = 0.125f; }
    else if (z == 1) { Ohi = g_khi; Olo = g_klo; scale = 1.0f; }
    else             { Ohi = g_vhi; Olo = g_vlo; scale = 1.0f; }

    GemmFrag fr;
    hmma_core(g_xhi, g_xlo, g_whi[z], g_wlo[z], blockIdx.y * 128, blockIdx.x * 128, fr);

    const int bm = blockIdx.y * 128, bn = blockIdx.x * 128;
#pragma unroll
    for (int mi = 0; mi < 4; mi++) {
        int row = bm + fr.wm + mi * 16 + (fr.lane >> 2);
#pragma unroll
        for (int ni = 0; ni < 4; ni++) {
            int col = bn + fr.wn + ni * 8 + ((fr.lane & 3) << 1);
            uint32_t h0, l0, h1, l1;
            split2(fr.acc[mi][ni][0] * scale, fr.acc[mi][ni][1] * scale, h0, l0);
            split2(fr.acc[mi][ni][2] * scale, fr.acc[mi][ni][3] * scale, h1, l1);
            *(uint32_t*)(Ohi + (size_t)row * HIDDEN + col) = h0;
            *(uint32_t*)(Olo + (size_t)row * HIDDEN + col) = l0;
            *(uint32_t*)(Ohi + (size_t)(row + 8) * HIDDEN + col) = h1;
            *(uint32_t*)(Olo + (size_t)(row + 8) * HIDDEN + col) = l1;
        }
    }
}

// proj: fp32 out
__global__ __launch_bounds__(256) void proj_mma_kernel(float* __restrict__ out)
{
    GemmFrag fr;
    hmma_core(g_chi, g_clo, g_whi[3], g_wlo[3], blockIdx.y * 128, blockIdx.x * 128, fr);

    const int bm = blockIdx.y * 128, bn = blockIdx.x * 128;
#pragma unroll
    for (int mi = 0; mi < 4; mi++) {
        int row = bm + fr.wm + mi * 16 + (fr.lane >> 2);
#pragma unroll
        for (int ni = 0; ni < 4; ni++) {
            int col = bn + fr.wn + ni * 8 + ((fr.lane & 3) << 1);
            *(float2*)(out + (size_t)row * HIDDEN + col) =
                make_float2(fr.acc[mi][ni][0], fr.acc[mi][ni][1]);
            *(float2*)(out + (size_t)(row + 8) * HIDDEN + col) =
                make_float2(fr.acc[mi][ni][2], fr.acc[mi][ni][3]);
        }
    }
}

// ---------------------------------------------------------------------------
// Tensor-core flash attention, cp.async double-buffered.
// CTA: 128 queries x one (b,h). 8 warps x 16 q-rows. Key tiles of 64.
// Dyn smem: 2 x 32KB buffers. Buffer layout (byte, rel.):
//   Khi 0, Klo 8192, Vhi 16384, Vlo 24576. Swizzle: chunk c ^ (row&7).
// ---------------------------------------------------------------------------
#define ATTN_SMEM 65536

__global__ __launch_bounds__(256) void attn_mma_kernel()
{
    const uint32_t sb = smem_u32(dynsm);

    const int tid  = threadIdx.x;
    const int lane = tid & 31;
    const int wid  = tid >> 5;
    const int bh   = blockIdx.y;
    const int b    = bh / NH;
    const int h    = bh % NH;
    const int q0   = blockIdx.x * 128;

    const size_t base = (size_t)b * SEQ * HIDDEN + h * DH;

    // ---- stage Q into buffer 0 via cp.async (hi at 0, lo at 16384) ----
    {
#pragma unroll
        for (int j = 0; j < 4; j++) {
            int idx = j * 256 + tid;
            int r = idx >> 3, c = idx & 7;
            uint32_t d = (uint32_t)(r * 8 + (c ^ (r & 7))) * 16;
            const uint4* qh = (const uint4*)(g_qhi + base + (size_t)(q0 + r) * HIDDEN);
            const uint4* ql = (const uint4*)(g_qlo + base + (size_t)(q0 + r) * HIDDEN);
            cp_async16(sb + d, qh + c);
            cp_async16(sb + 16384 + d, ql + c);
        }
    }
    CP_COMMIT();
    CP_WAIT(0);
    __syncthreads();

    // ---- Q fragments (held in registers for whole kernel) ----
    uint32_t qh[4][4], ql[4][4];
    {
        int qrow = wid * 16 + (lane & 15);
        int key  = qrow & 7;
#pragma unroll
        for (int ks = 0; ks < 4; ks++) {
            int c = ks * 2 + (lane >> 4);
            uint32_t off = (uint32_t)(qrow * 8 + (c ^ key)) * 16;
            ldsm_x4(qh[ks], sb + off);
            ldsm_x4(ql[ks], sb + 16384 + off);
        }
    }
    __syncthreads();

    float accO[8][4];
#pragma unroll
    for (int n = 0; n < 8; n++)
#pragma unroll
        for (int t = 0; t < 4; t++) accO[n][t] = 0.0f;
    float m0 = -CUDART_INF_F, m1 = -CUDART_INF_F, l0 = 0.0f, l1 = 0.0f;

    const int sr = tid >> 3;           // 0..31
    const int sc = tid & 7;
    const uint32_t sd0 = (uint32_t)(sr * 8 + (sc ^ (sr & 7))) * 16;
    const uint32_t sd1 = (uint32_t)((sr + 32) * 8 + (sc ^ (sr & 7))) * 16;

    auto stageKV = [&](int kt, int buf) {
        uint32_t d = sb + (uint32_t)buf * 32768;
        const uint4* kh0 = (const uint4*)(g_khi + base + (size_t)(kt + sr) * HIDDEN) + sc;
        const uint4* kh1 = (const uint4*)(g_khi + base + (size_t)(kt + 32 + sr) * HIDDEN) + sc;
        const uint4* kl0 = (const uint4*)(g_klo + base + (size_t)(kt + sr) * HIDDEN) + sc;
        const uint4* kl1 = (const uint4*)(g_klo + base + (size_t)(kt + 32 + sr) * HIDDEN) + sc;
        const uint4* vh0 = (const uint4*)(g_vhi + base + (size_t)(kt + sr) * HIDDEN) + sc;
        const uint4* vh1 = (const uint4*)(g_vhi + base + (size_t)(kt + 32 + sr) * HIDDEN) + sc;
        const uint4* vl0 = (const uint4*)(g_vlo + base + (size_t)(kt + sr) * HIDDEN) + sc;
        const uint4* vl1 = (const uint4*)(g_vlo + base + (size_t)(kt + 32 + sr) * HIDDEN) + sc;
        cp_async16(d + sd0,         kh0);
        cp_async16(d + sd1,         kh1);
        cp_async16(d + 8192 + sd0,  kl0);
        cp_async16(d + 8192 + sd1,  kl1);
        cp_async16(d + 16384 + sd0, vh0);
        cp_async16(d + 16384 + sd1, vh1);
        cp_async16(d + 24576 + sd0, vl0);
        cp_async16(d + 24576 + sd1, vl1);
    };

    stageKV(0, 0);
    CP_COMMIT();

    for (int it = 0; it < SEQ / 64; it++) {
        if (it + 1 < SEQ / 64) {
            stageKV((it + 1) * 64, (it + 1) & 1);
            CP_COMMIT();
            CP_WAIT(1);
        } else {
            CP_WAIT(0);
        }
        __syncthreads();

        const uint32_t bKh = sb + (uint32_t)(it & 1) * 32768;
        const uint32_t bKl = bKh + 8192;
        const uint32_t bVh = bKh + 16384;
        const uint32_t bVl = bKh + 24576;

        // ---- S = Q.K^T (3-term), ldmatrix x4 over ni-pairs ----
        float s[8][4];
#pragma unroll
        for (int n = 0; n < 8; n++)
#pragma unroll
            for (int t = 0; t < 4; t++) s[n][t] = 0.0f;

#pragma unroll
        for (int ks = 0; ks < 4; ks++) {
#pragma unroll
            for (int p = 0; p < 4; p++) {         // ni pair (2p, 2p+1)
                int krow = (2 * p + ((lane >> 4) & 1)) * 8 + (lane & 7);
                int c = ks * 2 + ((lane >> 3) & 1);
                uint32_t off = (uint32_t)(krow * 8 + (c ^ (lane & 7))) * 16;
                uint32_t kh4[4], kl4[4];
                ldsm_x4(kh4, bKh + off);
                ldsm_x4(kl4, bKl + off);
                mma_bf16(s[2 * p],     qh[ks], &kh4[0]);
                mma_bf16(s[2 * p],     qh[ks], &kl4[0]);
                mma_bf16(s[2 * p],     ql[ks], &kh4[0]);
                mma_bf16(s[2 * p + 1], qh[ks], &kh4[2]);
                mma_bf16(s[2 * p + 1], qh[ks], &kl4[2]);
                mma_bf16(s[2 * p + 1], ql[ks], &kh4[2]);
            }
        }

        // ---- online softmax (rows r = lane>>2 and r+8) ----
        float rmax0 = -CUDART_INF_F, rmax1 = -CUDART_INF_F;
#pragma unroll
        for (int n = 0; n < 8; n++) {
            rmax0 = fmaxf(rmax0, fmaxf(s[n][0], s[n][1]));
            rmax1 = fmaxf(rmax1, fmaxf(s[n][2], s[n][3]));
        }
        rmax0 = fmaxf(rmax0, __shfl_xor_sync(0xffffffffu, rmax0, 1));
        rmax0 = fmaxf(rmax0, __shfl_xor_sync(0xffffffffu, rmax0, 2));
        rmax1 = fmaxf(rmax1, __shfl_xor_sync(0xffffffffu, rmax1, 1));
        rmax1 = fmaxf(rmax1, __shfl_xor_sync(0xffffffffu, rmax1, 2));
        float mn0 = fmaxf(m0, rmax0), mn1 = fmaxf(m1, rmax1);
        float a0 = __expf(m0 - mn0), a1 = __expf(m1 - mn1);
        float sum0 = 0.0f, sum1 = 0.0f;
#pragma unroll
        for (int n = 0; n < 8; n++) {
            s[n][0] = __expf(s[n][0] - mn0);
            s[n][1] = __expf(s[n][1] - mn0);
            s[n][2] = __expf(s[n][2] - mn1);
            s[n][3] = __expf(s[n][3] - mn1);
            sum0 += s[n][0] + s[n][1];
            sum1 += s[n][2] + s[n][3];
        }
        sum0 += __shfl_xor_sync(0xffffffffu, sum0, 1);
        sum0 += __shfl_xor_sync(0xffffffffu, sum0, 2);
        sum1 += __shfl_xor_sync(0xffffffffu, sum1, 1);
        sum1 += __shfl_xor_sync(0xffffffffu, sum1, 2);
        l0 = l0 * a0 + sum0;
        l1 = l1 * a1 + sum1;
        m0 = mn0; m1 = mn1;
#pragma unroll
        for (int n = 0; n < 8; n++) {
            accO[n][0] *= a0; accO[n][1] *= a0;
            accO[n][2] *= a1; accO[n][3] *= a1;
        }

        // ---- pack P into A fragments (hi/lo) ----
        uint32_t ph[4][4], pl[4][4];
#pragma unroll
        for (int j = 0; j < 4; j++) {
            split2(s[2 * j][0],     s[2 * j][1],     ph[j][0], pl[j][0]);
            split2(s[2 * j][2],     s[2 * j][3],     ph[j][1], pl[j][1]);
            split2(s[2 * j + 1][0], s[2 * j + 1][1], ph[j][2], pl[j][2]);
            split2(s[2 * j + 1][2], s[2 * j + 1][3], ph[j][3], pl[j][3]);
        }

        // ---- O += P.V (3-term), V via ldmatrix.x4.trans over n2-pairs ----
#pragma unroll
        for (int j = 0; j < 4; j++) {
            int vrow = j * 16 + (lane & 15);
#pragma unroll
            for (int q = 0; q < 4; q++) {          // n2 pair (2q, 2q+1)
                int c = 2 * q + ((lane >> 4) & 1);
                uint32_t off = (uint32_t)(vrow * 8 + (c ^ (vrow & 7))) * 16;
                uint32_t vh4[4], vl4[4];
                ldsm_x4_t(vh4, bVh + off);
                ldsm_x4_t(vl4, bVl + off);
                mma_bf16(accO[2 * q],     ph[j], &vh4[0]);
                mma_bf16(accO[2 * q],     ph[j], &vl4[0]);
                mma_bf16(accO[2 * q],     pl[j], &vh4[0]);
                mma_bf16(accO[2 * q + 1], ph[j], &vh4[2]);
                mma_bf16(accO[2 * q + 1], ph[j], &vl4[2]);
                mma_bf16(accO[2 * q + 1], pl[j], &vh4[2]);
            }
        }
        __syncthreads();
    }

    // ---- epilogue: normalize, write ctx hi/lo bf16 ----
    float inv0 = 1.0f / l0, inv1 = 1.0f / l1;
    int row = q0 + wid * 16 + (lane >> 2);
#pragma unroll
    for (int n2 = 0; n2 < 8; n2++) {
        int col = n2 * 8 + ((lane & 3) << 1);
        uint32_t h0, lo0, h1, lo1;
        split2(accO[n2][0] * inv0, accO[n2][1] * inv0, h0, lo0);
        split2(accO[n2][2] * inv1, accO[n2][3] * inv1, h1, lo1);
        size_t p0 = base + (size_t)row * HIDDEN + col;
        size_t p1 = base + (size_t)(row + 8) * HIDDEN + col;
        *(uint32_t*)(g_chi + p0) = h0;
        *(uint32_t*)(g_clo + p0) = lo0;
        *(uint32_t*)(g_chi + p1) = h1;
        *(uint32_t*)(g_clo + p1) = lo1;
    }
}

// ---------------------------------------------------------------------------
extern "C" void kernel_launch(void* const* d_in, const int* in_sizes, int n_in,
                              void* d_out, int out_size)
{
    const float* x  = (const float*)d_in[0];
    const float* wq = (const float*)d_in[1];
    const float* wk = (const float*)d_in[2];
    const float* wv = (const float*)d_in[3];
    const float* wo = (const float*)d_in[4];
    float* out = (float*)d_out;

    cudaFuncSetAttribute(qkv_mma_kernel, cudaFuncAttributeMaxDynamicSharedMemorySize,
                         GEMM_SMEM);
    cudaFuncSetAttribute(proj_mma_kernel, cudaFuncAttributeMaxDynamicSharedMemorySize,
                         GEMM_SMEM);
    cudaFuncSetAttribute(attn_mma_kernel, cudaFuncAttributeMaxDynamicSharedMemorySize,
                         ATTN_SMEM);

    const int nx4 = MTOT * HIDDEN / 4;
    const int nw4 = HIDDEN * HIDDEN / 4;

    split_x_kernel<<<(nx4 + 255) / 256, 256>>>(x);
    dim3 gsw((nw4 + 255) / 256, 4);
    split_w_kernel<<<gsw, 256>>>(wq, wk, wv, wo);

    dim3 gqkv(HIDDEN / 128, MTOT / 128, 3);    // (6, 64, 3)
    qkv_mma_kernel<<<gqkv, 256, GEMM_SMEM>>>();

    dim3 gattn(SEQ / 128, BATCH * NH);         // (16, 48)
    attn_mma_kernel<<<gattn, 256, ATTN_SMEM>>>();

    dim3 gproj(HIDDEN / 128, MTOT / 128);      // (6, 64)
    proj_mma_kernel<<<gproj, 256, GEMM_SMEM>>>(out);
}